// round 1
// baseline (speedup 1.0000x reference)
#include <cuda_runtime.h>

#define NTH 256
#define MAXBLK 4096
#define CAP 262144

// block-partial objective sums: o[t] for t=0..10, one slot per block
__device__ double g_part[11 * MAXBLK];
__device__ int    g_K;
// stashed s_10 trajectory endpoint: x part [0, 2*CAP), y part [2*CAP, 5*CAP)
__device__ float  g_state[5 * CAP];

__device__ __forceinline__ float objf(float x1, float x2, float y1, float y2, float y3) {
    float o = 0.f;
#define TERM(xx, yy) { float a_ = (xx) + (yy); o = fmaf(a_, a_, o); \
                       float m_ = (xx) * (yy); o = fmaf(m_, m_, o); }
    TERM(x1, y1) TERM(x2, y1)
    TERM(x1, y2) TERM(x2, y2)
    TERM(x1, y3) TERM(x2, y3)
#undef TERM
    return o;
}

// One Gauss-Newton step: solve (J^T J) u = J^T r via 2x2 Schur complement,
// then (x,y) -= u.  J^T J = [[A*I2, C],[C^T, B*I3]] with
//   A = 3 + S2, B = 2 + Q, C[j][i] = 1 + x_j*y_i
// J^T r: gx_j = 3 x_j + S1 + x_j S2 ;  gy_i = (x1+x2) + (2+Q) y_i
__device__ __forceinline__ void gn_step(float& x1, float& x2,
                                        float& y1, float& y2, float& y3) {
    float S1 = y1 + y2 + y3;
    float S2 = fmaf(y1, y1, fmaf(y2, y2, y3 * y3));
    float Q  = fmaf(x1, x1, x2 * x2);
    float P1 = x1 + x2;
    float A  = 3.0f + S2;
    float Bv = 2.0f + Q;

    float c11 = fmaf(x1, y1, 1.f), c12 = fmaf(x1, y2, 1.f), c13 = fmaf(x1, y3, 1.f);
    float c21 = fmaf(x2, y1, 1.f), c22 = fmaf(x2, y2, 1.f), c23 = fmaf(x2, y3, 1.f);

    float gx1 = fmaf(x1, S2, fmaf(3.f, x1, S1));
    float gx2 = fmaf(x2, S2, fmaf(3.f, x2, S1));
    float gy1 = fmaf(Bv, y1, P1);
    float gy2 = fmaf(Bv, y2, P1);
    float gy3 = fmaf(Bv, y3, P1);

    float invB = 1.0f / Bv;   // Bv >= 2, always safe

    float cc11 = fmaf(c11, c11, fmaf(c12, c12, c13 * c13));
    float cc12 = fmaf(c11, c21, fmaf(c12, c22, c13 * c23));
    float cc22 = fmaf(c21, c21, fmaf(c22, c22, c23 * c23));

    float s11 = fmaf(-cc11, invB, A);
    float s12 = -cc12 * invB;
    float s22 = fmaf(-cc22, invB, A);

    float r1 = fmaf(-invB, fmaf(c11, gy1, fmaf(c12, gy2, c13 * gy3)), gx1);
    float r2 = fmaf(-invB, fmaf(c21, gy1, fmaf(c22, gy2, c23 * gy3)), gx2);

    float det  = fmaf(s11, s22, -(s12 * s12));
    float invd = 1.0f / det;

    float ux1 = fmaf(s22, r1, -(s12 * r2)) * invd;
    float ux2 = fmaf(s11, r2, -(s12 * r1)) * invd;

    float uy1 = (gy1 - fmaf(c11, ux1, c21 * ux2)) * invB;
    float uy2 = (gy2 - fmaf(c12, ux1, c22 * ux2)) * invB;
    float uy3 = (gy3 - fmaf(c13, ux1, c23 * ux2)) * invB;

    x1 -= ux1; x2 -= ux2;
    y1 -= uy1; y2 -= uy2; y3 -= uy3;
}

// K1: run the full unconditional GN trajectory per example; emit block-partial
// objective sums o_0..o_10 and stash s_10.
__global__ void __launch_bounds__(NTH)
k_obj(const float* __restrict__ xin, const float* __restrict__ yin, int B) {
    int b = blockIdx.x * NTH + threadIdx.x;
    float x1 = 0.f, x2 = 0.f, y1 = 0.f, y2 = 0.f, y3 = 0.f;
    if (b < B) {
        float2 xv = *reinterpret_cast<const float2*>(xin + 2 * b);
        x1 = xv.x; x2 = xv.y;
        y1 = yin[3 * b]; y2 = yin[3 * b + 1]; y3 = yin[3 * b + 2];
    }
    // zeros stay zeros through gn_step, objective 0 -> padding threads contribute 0

    float o[11];
#pragma unroll
    for (int t = 0; t < 10; t++) {
        o[t] = objf(x1, x2, y1, y2, y3);
        gn_step(x1, x2, y1, y2, y3);
    }
    o[10] = objf(x1, x2, y1, y2, y3);

    if (b < B && b < CAP) {
        g_state[2 * b]     = x1;
        g_state[2 * b + 1] = x2;
        g_state[2 * CAP + 3 * b]     = y1;
        g_state[2 * CAP + 3 * b + 1] = y2;
        g_state[2 * CAP + 3 * b + 2] = y3;
    }

    // block reduction of the 11 objective partials
    int lane = threadIdx.x & 31;
    int wid  = threadIdx.x >> 5;
    __shared__ float sm[NTH / 32];
#pragma unroll
    for (int t = 0; t < 11; t++) {
        float v = o[t];
#pragma unroll
        for (int off = 16; off > 0; off >>= 1)
            v += __shfl_down_sync(0xffffffffu, v, off);
        if (lane == 0) sm[wid] = v;
        __syncthreads();
        if (wid == 0) {
            float w = (lane < (NTH / 32)) ? sm[lane] : 0.f;
#pragma unroll
            for (int off = 4; off > 0; off >>= 1)
                w += __shfl_down_sync(0xffffffffu, w, off);
            if (lane == 0) g_part[t * MAXBLK + blockIdx.x] = (double)w;
        }
        __syncthreads();
    }
}

// K2: single-block deterministic reduction of block partials + accept-prefix scan.
__global__ void k_decide(int nblk) {
    __shared__ double red[256];
    __shared__ double osum[11];
    int tid = threadIdx.x;
    for (int t = 0; t < 11; t++) {
        double s = 0.0;
        for (int i = tid; i < nblk; i += 256) s += g_part[t * MAXBLK + i];
        red[tid] = s;
        __syncthreads();
        for (int off = 128; off > 0; off >>= 1) {
            if (tid < off) red[tid] += red[tid + off];
            __syncthreads();
        }
        if (tid == 0) osum[t] = red[0];
        __syncthreads();
    }
    if (tid == 0) {
        double obj = osum[0];
        int K = 0;
        for (int t = 1; t <= 10; t++) {
            if (osum[t] < obj) { obj = osum[t]; K = t; }
            else break;   // a reject freezes the state forever (reg is a fp32 no-op)
        }
        g_K = K;
    }
}

// K3: write s_K. Fast path: K==10 -> copy the stashed endpoint.
__global__ void __launch_bounds__(NTH)
k_out(const float* __restrict__ xin, const float* __restrict__ yin,
      float* __restrict__ out, int B) {
    int b = blockIdx.x * NTH + threadIdx.x;
    if (b >= B) return;
    int K = g_K;
    float x1, x2, y1, y2, y3;
    if (K == 10 && B <= CAP) {
        x1 = g_state[2 * b];
        x2 = g_state[2 * b + 1];
        y1 = g_state[2 * CAP + 3 * b];
        y2 = g_state[2 * CAP + 3 * b + 1];
        y3 = g_state[2 * CAP + 3 * b + 2];
    } else {
        float2 xv = *reinterpret_cast<const float2*>(xin + 2 * b);
        x1 = xv.x; x2 = xv.y;
        y1 = yin[3 * b]; y2 = yin[3 * b + 1]; y3 = yin[3 * b + 2];
        for (int t = 0; t < K; t++) gn_step(x1, x2, y1, y2, y3);
    }
    out[2 * b]     = x1;
    out[2 * b + 1] = x2;
    out[2 * B + 3 * b]     = y1;
    out[2 * B + 3 * b + 1] = y2;
    out[2 * B + 3 * b + 2] = y3;
}

extern "C" void kernel_launch(void* const* d_in, const int* in_sizes, int n_in,
                              void* d_out, int out_size) {
    const float* x = (const float*)d_in[0];   // (B,1,2) float32
    const float* y = (const float*)d_in[1];   // (B,3,1) float32
    int B = in_sizes[0] / 2;
    int nblk = (B + NTH - 1) / NTH;           // 1024 for B=262144 (<= MAXBLK)

    k_obj<<<nblk, NTH>>>(x, y, B);
    k_decide<<<1, 256>>>(nblk);
    k_out<<<nblk, NTH>>>(x, y, (float*)d_out, B);
}

// round 2
// speedup vs baseline: 1.0342x; 1.0342x over previous
#include <cuda_runtime.h>

#define NTH 256
#define ITEMS 2
#define MAXBLK 4096

__device__ double g_part[11 * MAXBLK];
__device__ int    g_K;

__device__ __forceinline__ float frcp(float a) {
    float r; asm("rcp.approx.f32 %0, %1;" : "=f"(r) : "f"(a)); return r;
}

__device__ __forceinline__ float objf(float x1, float x2, float y1, float y2, float y3) {
    float o = 0.f;
#define TERM(xx, yy) { float a_ = (xx) + (yy); o = fmaf(a_, a_, o); \
                       float m_ = (xx) * (yy); o = fmaf(m_, m_, o); }
    TERM(x1, y1) TERM(x2, y1)
    TERM(x1, y2) TERM(x2, y2)
    TERM(x1, y3) TERM(x2, y3)
#undef TERM
    return o;
}

// One Gauss-Newton step via 2x2 Schur complement of the arrow-structured J^T J.
__device__ __forceinline__ void gn_step(float& x1, float& x2,
                                        float& y1, float& y2, float& y3) {
    float S1 = y1 + y2 + y3;
    float S2 = fmaf(y1, y1, fmaf(y2, y2, y3 * y3));
    float Q  = fmaf(x1, x1, x2 * x2);
    float P1 = x1 + x2;
    float A  = 3.0f + S2;
    float Bv = 2.0f + Q;

    float c11 = fmaf(x1, y1, 1.f), c12 = fmaf(x1, y2, 1.f), c13 = fmaf(x1, y3, 1.f);
    float c21 = fmaf(x2, y1, 1.f), c22 = fmaf(x2, y2, 1.f), c23 = fmaf(x2, y3, 1.f);

    float gx1 = fmaf(x1, S2, fmaf(3.f, x1, S1));
    float gx2 = fmaf(x2, S2, fmaf(3.f, x2, S1));
    float gy1 = fmaf(Bv, y1, P1);
    float gy2 = fmaf(Bv, y2, P1);
    float gy3 = fmaf(Bv, y3, P1);

    float invB = frcp(Bv);   // Bv >= 2, always safe

    float cc11 = fmaf(c11, c11, fmaf(c12, c12, c13 * c13));
    float cc12 = fmaf(c11, c21, fmaf(c12, c22, c13 * c23));
    float cc22 = fmaf(c21, c21, fmaf(c22, c22, c23 * c23));

    float s11 = fmaf(-cc11, invB, A);
    float s12 = -cc12 * invB;
    float s22 = fmaf(-cc22, invB, A);

    float r1 = fmaf(-invB, fmaf(c11, gy1, fmaf(c12, gy2, c13 * gy3)), gx1);
    float r2 = fmaf(-invB, fmaf(c21, gy1, fmaf(c22, gy2, c23 * gy3)), gx2);

    float det  = fmaf(s11, s22, -(s12 * s12));
    float invd = frcp(det);

    float ux1 = fmaf(s22, r1, -(s12 * r2)) * invd;
    float ux2 = fmaf(s11, r2, -(s12 * r1)) * invd;

    float uy1 = (gy1 - fmaf(c11, ux1, c21 * ux2)) * invB;
    float uy2 = (gy2 - fmaf(c12, ux1, c22 * ux2)) * invB;
    float uy3 = (gy3 - fmaf(c13, ux1, c23 * ux2)) * invB;

    x1 -= ux1; x2 -= ux2;
    y1 -= uy1; y2 -= uy2; y3 -= uy3;
}

// K1: 2 items/thread, single wave. Runs the full unconditional GN trajectory,
// emits block-partial objective sums o_0..o_10, writes s_10 straight to d_out.
__global__ void __launch_bounds__(NTH, 4)
k_obj(const float* __restrict__ xin, const float* __restrict__ yin,
      float* __restrict__ out, int B) {
    int base = blockIdx.x * (NTH * ITEMS) + threadIdx.x;

    float X1[ITEMS], X2[ITEMS], Y1[ITEMS], Y2[ITEMS], Y3[ITEMS];
    bool  valid[ITEMS];
#pragma unroll
    for (int i = 0; i < ITEMS; i++) {
        int b = base + i * NTH;
        valid[i] = (b < B);
        if (valid[i]) {
            float2 xv = *reinterpret_cast<const float2*>(xin + 2 * b);
            X1[i] = xv.x; X2[i] = xv.y;
            Y1[i] = yin[3 * b]; Y2[i] = yin[3 * b + 1]; Y3[i] = yin[3 * b + 2];
        } else {
            X1[i] = 1.f; X2[i] = 0.f; Y1[i] = 1.f; Y2[i] = 0.f; Y3[i] = 0.f;
        }
    }

    float o[11];
#pragma unroll
    for (int t = 0; t < 10; t++) {
        float acc = 0.f;
#pragma unroll
        for (int i = 0; i < ITEMS; i++)
            acc += valid[i] ? objf(X1[i], X2[i], Y1[i], Y2[i], Y3[i]) : 0.f;
        o[t] = acc;
#pragma unroll
        for (int i = 0; i < ITEMS; i++)
            gn_step(X1[i], X2[i], Y1[i], Y2[i], Y3[i]);
    }
    {
        float acc = 0.f;
#pragma unroll
        for (int i = 0; i < ITEMS; i++)
            acc += valid[i] ? objf(X1[i], X2[i], Y1[i], Y2[i], Y3[i]) : 0.f;
        o[10] = acc;
    }

    // s_10 -> d_out directly (overwritten later only if K < 10)
#pragma unroll
    for (int i = 0; i < ITEMS; i++) {
        int b = base + i * NTH;
        if (valid[i]) {
            out[2 * b]     = X1[i];
            out[2 * b + 1] = X2[i];
            out[2 * B + 3 * b]     = Y1[i];
            out[2 * B + 3 * b + 1] = Y2[i];
            out[2 * B + 3 * b + 2] = Y3[i];
        }
    }

    // block reduction, single __syncthreads
    int lane = threadIdx.x & 31;
    int wid  = threadIdx.x >> 5;
    __shared__ float sm[(NTH / 32)][11];
#pragma unroll
    for (int t = 0; t < 11; t++) {
        float v = o[t];
#pragma unroll
        for (int off = 16; off > 0; off >>= 1)
            v += __shfl_down_sync(0xffffffffu, v, off);
        if (lane == 0) sm[wid][t] = v;
    }
    __syncthreads();
    if (wid == 0) {
#pragma unroll
        for (int t = 0; t < 11; t++) {
            float w = (lane < (NTH / 32)) ? sm[lane][t] : 0.f;
#pragma unroll
            for (int off = 4; off > 0; off >>= 1)
                w += __shfl_down_sync(0xffffffffu, w, off);
            if (lane == 0) g_part[t * MAXBLK + blockIdx.x] = (double)w;
        }
    }
}

// K2: single-block deterministic reduction + accept-prefix scan.
__global__ void k_decide(int nblk) {
    __shared__ double red[256];
    __shared__ double osum[11];
    int tid = threadIdx.x;
    for (int t = 0; t < 11; t++) {
        double s = 0.0;
        for (int i = tid; i < nblk; i += 256) s += g_part[t * MAXBLK + i];
        red[tid] = s;
        __syncthreads();
        for (int off = 128; off > 0; off >>= 1) {
            if (tid < off) red[tid] += red[tid + off];
            __syncthreads();
        }
        if (tid == 0) osum[t] = red[0];
        __syncthreads();
    }
    if (tid == 0) {
        double obj = osum[0];
        int K = 0;
        for (int t = 1; t <= 10; t++) {
            if (osum[t] < obj) { obj = osum[t]; K = t; }
            else break;   // a reject freezes the state forever (reg is a fp32 no-op)
        }
        g_K = K;
    }
}

// K3: fixup only when K < 10 (rare path); common case is an early-exit stub.
__global__ void __launch_bounds__(NTH)
k_out(const float* __restrict__ xin, const float* __restrict__ yin,
      float* __restrict__ out, int B) {
    int K = g_K;
    if (K == 10) return;
    int b = blockIdx.x * NTH + threadIdx.x;
    if (b >= B) return;
    float2 xv = *reinterpret_cast<const float2*>(xin + 2 * b);
    float x1 = xv.x, x2 = xv.y;
    float y1 = yin[3 * b], y2 = yin[3 * b + 1], y3 = yin[3 * b + 2];
    for (int t = 0; t < K; t++) gn_step(x1, x2, y1, y2, y3);
    out[2 * b]     = x1;
    out[2 * b + 1] = x2;
    out[2 * B + 3 * b]     = y1;
    out[2 * B + 3 * b + 1] = y2;
    out[2 * B + 3 * b + 2] = y3;
}

extern "C" void kernel_launch(void* const* d_in, const int* in_sizes, int n_in,
                              void* d_out, int out_size) {
    const float* x = (const float*)d_in[0];   // (B,1,2) float32
    const float* y = (const float*)d_in[1];   // (B,3,1) float32
    int B = in_sizes[0] / 2;
    int nblk1 = (B + NTH * ITEMS - 1) / (NTH * ITEMS);   // 512 for B=262144
    int nblk3 = (B + NTH - 1) / NTH;

    k_obj<<<nblk1, NTH>>>(x, y, (float*)d_out, B);
    k_decide<<<1, 256>>>(nblk1);
    k_out<<<nblk3, NTH>>>(x, y, (float*)d_out, B);
}